// round 2
// baseline (speedup 1.0000x reference)
#include <cuda_runtime.h>
#include <cstdint>

#define NLEV   3
#define KCODES 512
#define DIM    1024
#define NTOK   65536           // 16 * 4096
#define DECAY  0.99f
#define OMD    0.01f           // (1 - DECAY) rounded to f32 == float(0.01)
#define EPSV   1e-5f

// ---- scratch (no allocations allowed; __device__ globals are the sanctioned path) ----
static __device__ float  g_residual[(size_t)NTOK * DIM];      // 268 MB
static __device__ float  g_sums[NLEV * KCODES * DIM];         // 6 MB
static __device__ float  g_counts[NLEV * KCODES];
static __device__ float  g_c2[NLEV * KCODES];
static __device__ float  g_cs[NLEV * KCODES];
static __device__ float  g_n[NLEV];
static __device__ double g_loss_acc[NLEV];
static __device__ int    g_idx[NTOK];

// ---------------------------------------------------------------- zero scratch
__global__ void k_zero() {
    int i = blockIdx.x * blockDim.x + threadIdx.x;
    if (i < NLEV * KCODES * DIM) g_sums[i] = 0.f;
    if (i < NLEV * KCODES)       g_counts[i] = 0.f;
    if (i < NLEV)                g_loss_acc[i] = 0.0;
}

// ---------------------------------------------------------------- ||C_k||^2
__global__ void k_c2(const float* __restrict__ codebooks) {
    int w    = (blockIdx.x * blockDim.x + threadIdx.x) >> 5;
    int lane = threadIdx.x & 31;
    if (w >= NLEV * KCODES) return;
    const float* row = codebooks + (size_t)w * DIM;
    float s = 0.f;
#pragma unroll
    for (int it = 0; it < DIM / 128; it++) {
        float4 v = *(const float4*)(row + lane * 4 + it * 128);
        s += v.x * v.x + v.y * v.y + v.z * v.z + v.w * v.w;
    }
#pragma unroll
    for (int o = 16; o; o >>= 1) s += __shfl_xor_sync(0xffffffffu, s, o);
    if (lane == 0) g_c2[w] = s;
}

// ---------------------------------------------------------------- assign (argmin)
// 64-token x 64-code tile, 256 threads, 4x4 register tile per thread,
// D streamed in chunks of 32 through SMEM (transposed for float4 loads).
__global__ void __launch_bounds__(256) k_assign(int level,
                                                const float* __restrict__ z_e,
                                                const float* __restrict__ codebooks,
                                                float* __restrict__ out_idx) {
    const float* resid = level ? g_residual : z_e;
    const float* cb    = codebooks + (size_t)level * KCODES * DIM;
    const float* c2    = g_c2 + level * KCODES;
    const int t0 = blockIdx.x * 64;

    __shared__ float4 sT4[32][16];   // [d][token/4]
    __shared__ float4 sC4[32][16];   // [d][code/4]
    __shared__ float  sr2[64];
    float* sTf = (float*)sT4;
    float* sCf = (float*)sC4;

    const int warp = threadIdx.x >> 5, lane = threadIdx.x & 31;

    // per-token ||r||^2
    for (int t = warp; t < 64; t += 8) {
        const float* r = resid + (size_t)(t0 + t) * DIM + lane * 4;
        float s = 0.f;
#pragma unroll
        for (int it = 0; it < 8; it++) {
            float4 v = *(const float4*)(r + it * 128);
            s += v.x * v.x + v.y * v.y + v.z * v.z + v.w * v.w;
        }
#pragma unroll
        for (int o = 16; o; o >>= 1) s += __shfl_xor_sync(0xffffffffu, s, o);
        if (lane == 0) sr2[t] = s;
    }

    const int tx = threadIdx.x & 15;        // code group
    const int ty = threadIdx.x >> 4;        // token group
    const int lt = threadIdx.x & 63;        // load: token/code row
    const int db = (threadIdx.x >> 6) * 8;  // load: d offset

    float cmin[4];
    int   cidx[4];
#pragma unroll
    for (int i = 0; i < 4; i++) { cmin[i] = 3.4e38f; cidx[i] = 0; }

    for (int ct = 0; ct < 8; ct++) {                 // 8 code tiles of 64
        float4 acc[4];
#pragma unroll
        for (int i = 0; i < 4; i++) acc[i] = make_float4(0.f, 0.f, 0.f, 0.f);

        for (int dc = 0; dc < 32; dc++) {            // 32 D-chunks of 32
            __syncthreads();
            const float* ts = resid + (size_t)(t0 + lt) * DIM + dc * 32 + db;
            float4 a0 = *(const float4*)(ts);
            float4 a1 = *(const float4*)(ts + 4);
            const float* csrc = cb + (size_t)(ct * 64 + lt) * DIM + dc * 32 + db;
            float4 b0 = *(const float4*)(csrc);
            float4 b1 = *(const float4*)(csrc + 4);
            sTf[(db + 0) * 64 + lt] = a0.x; sTf[(db + 1) * 64 + lt] = a0.y;
            sTf[(db + 2) * 64 + lt] = a0.z; sTf[(db + 3) * 64 + lt] = a0.w;
            sTf[(db + 4) * 64 + lt] = a1.x; sTf[(db + 5) * 64 + lt] = a1.y;
            sTf[(db + 6) * 64 + lt] = a1.z; sTf[(db + 7) * 64 + lt] = a1.w;
            sCf[(db + 0) * 64 + lt] = b0.x; sCf[(db + 1) * 64 + lt] = b0.y;
            sCf[(db + 2) * 64 + lt] = b0.z; sCf[(db + 3) * 64 + lt] = b0.w;
            sCf[(db + 4) * 64 + lt] = b1.x; sCf[(db + 5) * 64 + lt] = b1.y;
            sCf[(db + 6) * 64 + lt] = b1.z; sCf[(db + 7) * 64 + lt] = b1.w;
            __syncthreads();
#pragma unroll
            for (int d = 0; d < 32; d++) {
                float4 a = sT4[d][ty];
                float4 b = sC4[d][tx];
                acc[0].x += a.x * b.x; acc[0].y += a.x * b.y; acc[0].z += a.x * b.z; acc[0].w += a.x * b.w;
                acc[1].x += a.y * b.x; acc[1].y += a.y * b.y; acc[1].z += a.y * b.z; acc[1].w += a.y * b.w;
                acc[2].x += a.z * b.x; acc[2].y += a.z * b.y; acc[2].z += a.z * b.z; acc[2].w += a.z * b.w;
                acc[3].x += a.w * b.x; acc[3].y += a.w * b.y; acc[3].z += a.w * b.z; acc[3].w += a.w * b.w;
            }
        }

        // epilogue: distances + running argmin (first-min tie-break like jnp.argmin)
        float4 c2v = *(const float4*)(c2 + ct * 64 + tx * 4);
        const int base = ct * 64 + tx * 4;
#pragma unroll
        for (int i = 0; i < 4; i++) {
            float r2v = sr2[4 * ty + i];
            float d0 = r2v - 2.f * acc[i].x + c2v.x;
            float d1 = r2v - 2.f * acc[i].y + c2v.y;
            float d2 = r2v - 2.f * acc[i].z + c2v.z;
            float d3 = r2v - 2.f * acc[i].w + c2v.w;
            float mv = d0; int mi = base;
            if (d1 < mv) { mv = d1; mi = base + 1; }
            if (d2 < mv) { mv = d2; mi = base + 2; }
            if (d3 < mv) { mv = d3; mi = base + 3; }
#pragma unroll
            for (int off = 8; off; off >>= 1) {   // butterfly within the 16 tx lanes
                float ov = __shfl_xor_sync(0xffffffffu, mv, off);
                int   oi = __shfl_xor_sync(0xffffffffu, mi, off);
                if (ov < mv || (ov == mv && oi < mi)) { mv = ov; mi = oi; }
            }
            if (mv < cmin[i]) { cmin[i] = mv; cidx[i] = mi; }
        }
    }

    if (tx == 0) {
#pragma unroll
        for (int i = 0; i < 4; i++) {
            int tok = t0 + 4 * ty + i;
            g_idx[tok] = cidx[i];
            out_idx[(size_t)level * NTOK + tok] = (float)cidx[i];
        }
    }
}

// ---------------------------------------------------------------- update
// gather q, z_q accumulate, residual subtract, loss partial, EMA scatter stats
__global__ void __launch_bounds__(256) k_update(int level,
                                                const float* __restrict__ z_e,
                                                const float* __restrict__ codebooks,
                                                float* __restrict__ out_zq) {
    const int tok = blockIdx.x;
    const float* rin = level ? g_residual : z_e;
    const int idx = g_idx[tok];
    const float* q = codebooks + ((size_t)level * KCODES + idx) * DIM;
    const float* r = rin + (size_t)tok * DIM;
    float* sums = g_sums + ((size_t)level * KCODES + idx) * DIM;

    const int d = threadIdx.x * 4;
    float4 rv = *(const float4*)(r + d);
    float4 qv = *(const float4*)(q + d);
    float4 rq = make_float4(rv.x - qv.x, rv.y - qv.y, rv.z - qv.z, rv.w - qv.w);
    *(float4*)(g_residual + (size_t)tok * DIM + d) = rq;

    float* zo = out_zq + (size_t)tok * DIM + d;
    if (level) {
        float4 z = *(const float4*)zo;
        z.x += qv.x; z.y += qv.y; z.z += qv.z; z.w += qv.w;
        *(float4*)zo = z;
    } else {
        *(float4*)zo = qv;
    }

    atomicAdd(sums + d + 0, rv.x);
    atomicAdd(sums + d + 1, rv.y);
    atomicAdd(sums + d + 2, rv.z);
    atomicAdd(sums + d + 3, rv.w);
    if (threadIdx.x == 0) atomicAdd(g_counts + level * KCODES + idx, 1.0f);

    float ls = rq.x * rq.x + rq.y * rq.y + rq.z * rq.z + rq.w * rq.w;
#pragma unroll
    for (int o = 16; o; o >>= 1) ls += __shfl_xor_sync(0xffffffffu, ls, o);
    __shared__ float red[8];
    const int warp = threadIdx.x >> 5, lane = threadIdx.x & 31;
    if (lane == 0) red[warp] = ls;
    __syncthreads();
    if (threadIdx.x < 8) {
        float v = red[threadIdx.x];
#pragma unroll
        for (int o = 4; o; o >>= 1) v += __shfl_xor_sync(0xffu, v, o);
        if (threadIdx.x == 0) atomicAdd(&g_loss_acc[level], (double)v);
    }
}

// ---------------------------------------------------------------- cs + n
__global__ void k_csn(const float* __restrict__ ema_cluster) {
    const int l = blockIdx.x;
    const int k = threadIdx.x;   // 512 threads
    float cs = DECAY * ema_cluster[l * KCODES + k] + OMD * g_counts[l * KCODES + k];
    g_cs[l * KCODES + k] = cs;
    float s = cs;
#pragma unroll
    for (int o = 16; o; o >>= 1) s += __shfl_xor_sync(0xffffffffu, s, o);
    __shared__ float red[16];
    const int warp = threadIdx.x >> 5, lane = threadIdx.x & 31;
    if (lane == 0) red[warp] = s;
    __syncthreads();
    if (threadIdx.x < 16) {
        float v = red[threadIdx.x];
#pragma unroll
        for (int o = 8; o; o >>= 1) v += __shfl_xor_sync(0xffffu, v, o);
        if (threadIdx.x == 0) g_n[l] = v;
    }
}

// ---------------------------------------------------------------- new codebooks + loss
__global__ void k_cb(const float* __restrict__ ema_w,
                     float* __restrict__ out_cb,
                     float* __restrict__ out_loss) {
    const int i = blockIdx.x * blockDim.x + threadIdx.x;
    if (i == 0) {
        double L = (0.25 * g_loss_acc[0] + 0.5 * g_loss_acc[1] + 1.0 * g_loss_acc[2])
                   * (1.0 / ((double)NTOK * (double)DIM));
        *out_loss = (float)L;
    }
    if (i >= NLEV * KCODES * DIM) return;
    const int row = i >> 10;   // / DIM
    const int l   = row >> 9;  // / KCODES
    float w  = DECAY * ema_w[i] + OMD * g_sums[i];
    float cs = g_cs[row];
    float n  = g_n[l];
    float csn = (cs + EPSV) / (n + 0.00512f) * n;   // K*EPS = 512e-5
    out_cb[i] = w / csn;
}

// ---------------------------------------------------------------- launch
extern "C" void kernel_launch(void* const* d_in, const int* in_sizes, int n_in,
                              void* d_out, int out_size) {
    const float* z_e         = (const float*)d_in[0];
    const float* codebooks   = (const float*)d_in[1];
    const float* ema_cluster = (const float*)d_in[2];
    const float* ema_w       = (const float*)d_in[3];
    float* out = (float*)d_out;

    const size_t ZQ = (size_t)NTOK * DIM;
    float* out_zq   = out;
    float* out_loss = out + ZQ;
    float* out_idx  = out + ZQ + 1;
    float* out_cb   = out + ZQ + 1 + (size_t)NLEV * NTOK;

    k_zero<<<(NLEV * KCODES * DIM + 255) / 256, 256>>>();
    k_c2<<<(NLEV * KCODES * 32 + 255) / 256, 256>>>(codebooks);
    for (int l = 0; l < NLEV; l++) {
        k_assign<<<NTOK / 64, 256>>>(l, z_e, codebooks, out_idx);
        k_update<<<NTOK, 256>>>(l, z_e, codebooks, out_zq);
    }
    k_csn<<<NLEV, 512>>>(ema_cluster);
    k_cb<<<(NLEV * KCODES * DIM + 255) / 256, 256>>>(ema_w, out_cb, out_loss);
}

// round 3
// speedup vs baseline: 1.4601x; 1.4601x over previous
#include <cuda_runtime.h>
#include <cstdint>

#define NLEV   3
#define KCODES 512
#define DIM    1024
#define NTOK   65536           // 16 * 4096
#define DECAY  0.99f
#define OMD    0.01f
#define EPSV   1e-5f

typedef unsigned long long ull;

// ---- scratch (__device__ globals: the sanctioned no-alloc path) ----
static __device__ float  g_residual[(size_t)NTOK * DIM];      // 268 MB
static __device__ float  g_sums[NLEV * KCODES * DIM];         // 6 MB
static __device__ float  g_counts[NLEV * KCODES];
static __device__ float  g_c2[NLEV * KCODES];
static __device__ float  g_cs[NLEV * KCODES];
static __device__ float  g_n[NLEV];
static __device__ double g_loss_acc[NLEV];
static __device__ int    g_idx[NTOK];

// packed fp32x2 FMA: c.lo += a.lo*b.lo ; c.hi += a.hi*b.hi  (exact fp32 per lane)
__device__ __forceinline__ void ffma2(ull& c, ull a, ull b) {
    asm("fma.rn.f32x2 %0, %1, %2, %0;" : "+l"(c) : "l"(a), "l"(b));
}

union U4 { float4 f; ull u[2]; };
union U2 { ull u; float f[2]; };

// ---------------------------------------------------------------- zero scratch
__global__ void k_zero() {
    int i = blockIdx.x * blockDim.x + threadIdx.x;
    if (i < NLEV * KCODES * DIM) g_sums[i] = 0.f;
    if (i < NLEV * KCODES)       g_counts[i] = 0.f;
    if (i < NLEV)                g_loss_acc[i] = 0.0;
}

// ---------------------------------------------------------------- ||C_k||^2
__global__ void k_c2(const float* __restrict__ codebooks) {
    int w    = (blockIdx.x * blockDim.x + threadIdx.x) >> 5;
    int lane = threadIdx.x & 31;
    if (w >= NLEV * KCODES) return;
    const float* row = codebooks + (size_t)w * DIM;
    float s = 0.f;
#pragma unroll
    for (int it = 0; it < DIM / 128; it++) {
        float4 v = *(const float4*)(row + lane * 4 + it * 128);
        s += v.x * v.x + v.y * v.y + v.z * v.z + v.w * v.w;
    }
#pragma unroll
    for (int o = 16; o; o >>= 1) s += __shfl_xor_sync(0xffffffffu, s, o);
    if (lane == 0) g_c2[w] = s;
}

// ---------------------------------------------------------------- assign (argmin)
// Block tile: 64 tokens x 128 codes. 256 threads; per-thread 4 tokens x 8 codes
// with f32x2-packed accumulators over d-pairs (even d in .lo, odd d in .hi).
// smem layout: [d-quad][row*4] (float4 per (row, d-quad)), rows padded +4 floats.
#define ST_STRIDE (64 * 4 + 4)     // 260 floats per d-quad row
#define SC_STRIDE (128 * 4 + 4)    // 516 floats per d-quad row

__global__ void __launch_bounds__(256, 2) k_assign(int level,
                                                   const float* __restrict__ z_e,
                                                   const float* __restrict__ codebooks,
                                                   float* __restrict__ out_idx) {
    const float* resid = level ? g_residual : z_e;
    const float* cb    = codebooks + (size_t)level * KCODES * DIM;
    const float* c2    = g_c2 + level * KCODES;
    const int t0 = blockIdx.x * 64;

    __shared__ float sT[8 * ST_STRIDE];
    __shared__ float sC[8 * SC_STRIDE];
    __shared__ float sr2[64];

    const int tid  = threadIdx.x;
    const int warp = tid >> 5, lane = tid & 31;

    // per-token ||r||^2
    for (int t = warp; t < 64; t += 8) {
        const float* r = resid + (size_t)(t0 + t) * DIM + lane * 4;
        float s = 0.f;
#pragma unroll
        for (int it = 0; it < 8; it++) {
            float4 v = *(const float4*)(r + it * 128);
            s += v.x * v.x + v.y * v.y + v.z * v.z + v.w * v.w;
        }
#pragma unroll
        for (int o = 16; o; o >>= 1) s += __shfl_xor_sync(0xffffffffu, s, o);
        if (lane == 0) sr2[t] = s;
    }

    const int tx = tid & 15;   // code lane: owns codes {j*16 + tx}
    const int ty = tid >> 4;   // token group: owns tokens {ty*4 + i}

    float cmin[4];
    int   cidx[4];
#pragma unroll
    for (int i = 0; i < 4; i++) { cmin[i] = 3.4e38f; cidx[i] = 0; }

    for (int ct = 0; ct < 4; ct++) {                 // 4 code tiles of 128
        ull acc[4][8];
#pragma unroll
        for (int i = 0; i < 4; i++)
#pragma unroll
            for (int j = 0; j < 8; j++) acc[i][j] = 0ull;

        for (int dc = 0; dc < 32; dc++) {            // 32 D-chunks of 32
            __syncthreads();
            // stage T: 512 float4 slots, coalesced (8 consecutive threads = one row chunk)
#pragma unroll
            for (int i = 0; i < 2; i++) {
                int s = tid + i * 256;
                int tok = s >> 3, dq = s & 7;
                float4 v = *(const float4*)(resid + (size_t)(t0 + tok) * DIM + dc * 32 + dq * 4);
                *(float4*)&sT[dq * ST_STRIDE + tok * 4] = v;
            }
            // stage C: 1024 float4 slots
#pragma unroll
            for (int i = 0; i < 4; i++) {
                int s = tid + i * 256;
                int code = s >> 3, dq = s & 7;
                float4 v = *(const float4*)(cb + (size_t)(ct * 128 + code) * DIM + dc * 32 + dq * 4);
                *(float4*)&sC[dq * SC_STRIDE + code * 4] = v;
            }
            __syncthreads();

#pragma unroll
            for (int dq = 0; dq < 8; dq++) {
                U4 A[4];
#pragma unroll
                for (int i = 0; i < 4; i++)
                    A[i].f = *(const float4*)&sT[dq * ST_STRIDE + (ty * 4 + i) * 4];
#pragma unroll
                for (int j = 0; j < 8; j++) {
                    U4 B;
                    B.f = *(const float4*)&sC[dq * SC_STRIDE + (j * 16 + tx) * 4];
#pragma unroll
                    for (int i = 0; i < 4; i++) {
                        ffma2(acc[i][j], A[i].u[0], B.u[0]);
                        ffma2(acc[i][j], A[i].u[1], B.u[1]);
                    }
                }
            }
        }

        // epilogue: distances + running argmin (lowest-index tie-break like jnp.argmin)
#pragma unroll
        for (int i = 0; i < 4; i++) {
            float r2v = sr2[ty * 4 + i];
            float mv = 3.4e38f; int mi = 0;
#pragma unroll
            for (int j = 0; j < 8; j++) {
                U2 a; a.u = acc[i][j];
                float dot = a.f[0] + a.f[1];
                int id = ct * 128 + j * 16 + tx;
                float dd = r2v - 2.f * dot + __ldg(c2 + id);
                if (dd < mv) { mv = dd; mi = id; }
            }
#pragma unroll
            for (int off = 8; off; off >>= 1) {      // butterfly within 16 tx lanes
                float ov = __shfl_xor_sync(0xffffffffu, mv, off);
                int   oi = __shfl_xor_sync(0xffffffffu, mi, off);
                if (ov < mv || (ov == mv && oi < mi)) { mv = ov; mi = oi; }
            }
            if (mv < cmin[i]) { cmin[i] = mv; cidx[i] = mi; }
        }
    }

    if (tx == 0) {
#pragma unroll
        for (int i = 0; i < 4; i++) {
            int tok = t0 + 4 * ty + i;
            g_idx[tok] = cidx[i];
            out_idx[(size_t)level * NTOK + tok] = (float)cidx[i];
        }
    }
}

// ---------------------------------------------------------------- update
__global__ void __launch_bounds__(256) k_update(int level,
                                                const float* __restrict__ z_e,
                                                const float* __restrict__ codebooks,
                                                float* __restrict__ out_zq) {
    const int tok = blockIdx.x;
    const float* rin = level ? g_residual : z_e;
    const int idx = g_idx[tok];
    const float* q = codebooks + ((size_t)level * KCODES + idx) * DIM;
    const float* r = rin + (size_t)tok * DIM;
    float* sums = g_sums + ((size_t)level * KCODES + idx) * DIM;

    const int d = threadIdx.x * 4;
    float4 rv = *(const float4*)(r + d);
    float4 qv = *(const float4*)(q + d);
    float4 rq = make_float4(rv.x - qv.x, rv.y - qv.y, rv.z - qv.z, rv.w - qv.w);
    *(float4*)(g_residual + (size_t)tok * DIM + d) = rq;

    float* zo = out_zq + (size_t)tok * DIM + d;
    if (level) {
        float4 z = *(const float4*)zo;
        z.x += qv.x; z.y += qv.y; z.z += qv.z; z.w += qv.w;
        *(float4*)zo = z;
    } else {
        *(float4*)zo = qv;
    }

    atomicAdd(sums + d + 0, rv.x);
    atomicAdd(sums + d + 1, rv.y);
    atomicAdd(sums + d + 2, rv.z);
    atomicAdd(sums + d + 3, rv.w);
    if (threadIdx.x == 0) atomicAdd(g_counts + level * KCODES + idx, 1.0f);

    float ls = rq.x * rq.x + rq.y * rq.y + rq.z * rq.z + rq.w * rq.w;
#pragma unroll
    for (int o = 16; o; o >>= 1) ls += __shfl_xor_sync(0xffffffffu, ls, o);
    __shared__ float red[8];
    const int warp = threadIdx.x >> 5, lane = threadIdx.x & 31;
    if (lane == 0) red[warp] = ls;
    __syncthreads();
    if (threadIdx.x < 8) {
        float v = red[threadIdx.x];
#pragma unroll
        for (int o = 4; o; o >>= 1) v += __shfl_xor_sync(0xffu, v, o);
        if (threadIdx.x == 0) atomicAdd(&g_loss_acc[level], (double)v);
    }
}

// ---------------------------------------------------------------- cs + n
__global__ void k_csn(const float* __restrict__ ema_cluster) {
    const int l = blockIdx.x;
    const int k = threadIdx.x;   // 512 threads
    float cs = DECAY * ema_cluster[l * KCODES + k] + OMD * g_counts[l * KCODES + k];
    g_cs[l * KCODES + k] = cs;
    float s = cs;
#pragma unroll
    for (int o = 16; o; o >>= 1) s += __shfl_xor_sync(0xffffffffu, s, o);
    __shared__ float red[16];
    const int warp = threadIdx.x >> 5, lane = threadIdx.x & 31;
    if (lane == 0) red[warp] = s;
    __syncthreads();
    if (threadIdx.x < 16) {
        float v = red[threadIdx.x];
#pragma unroll
        for (int o = 8; o; o >>= 1) v += __shfl_xor_sync(0xffffu, v, o);
        if (threadIdx.x == 0) g_n[l] = v;
    }
}

// ---------------------------------------------------------------- new codebooks + loss
__global__ void k_cb(const float* __restrict__ ema_w,
                     float* __restrict__ out_cb,
                     float* __restrict__ out_loss) {
    const int i = blockIdx.x * blockDim.x + threadIdx.x;
    if (i == 0) {
        double L = (0.25 * g_loss_acc[0] + 0.5 * g_loss_acc[1] + 1.0 * g_loss_acc[2])
                   * (1.0 / ((double)NTOK * (double)DIM));
        *out_loss = (float)L;
    }
    if (i >= NLEV * KCODES * DIM) return;
    const int row = i >> 10;   // / DIM
    const int l   = row >> 9;  // / KCODES
    float w  = DECAY * ema_w[i] + OMD * g_sums[i];
    float cs = g_cs[row];
    float n  = g_n[l];
    float csn = (cs + EPSV) / (n + 0.00512f) * n;   // K*EPS = 512e-5
    out_cb[i] = w / csn;
}

// ---------------------------------------------------------------- launch
extern "C" void kernel_launch(void* const* d_in, const int* in_sizes, int n_in,
                              void* d_out, int out_size) {
    const float* z_e         = (const float*)d_in[0];
    const float* codebooks   = (const float*)d_in[1];
    const float* ema_cluster = (const float*)d_in[2];
    const float* ema_w       = (const float*)d_in[3];
    float* out = (float*)d_out;

    const size_t ZQ = (size_t)NTOK * DIM;
    float* out_zq   = out;
    float* out_loss = out + ZQ;
    float* out_idx  = out + ZQ + 1;
    float* out_cb   = out + ZQ + 1 + (size_t)NLEV * NTOK;

    k_zero<<<(NLEV * KCODES * DIM + 255) / 256, 256>>>();
    k_c2<<<(NLEV * KCODES * 32 + 255) / 256, 256>>>(codebooks);
    for (int l = 0; l < NLEV; l++) {
        k_assign<<<NTOK / 64, 256>>>(l, z_e, codebooks, out_idx);
        k_update<<<NTOK, 256>>>(l, z_e, codebooks, out_zq);
    }
    k_csn<<<NLEV, 512>>>(ema_cluster);
    k_cb<<<(NLEV * KCODES * DIM + 255) / 256, 256>>>(ema_w, out_cb, out_loss);
}